// round 15
// baseline (speedup 1.0000x reference)
#include <cuda_runtime.h>
#include <cuda_fp16.h>
#include <math.h>
#include <stdint.h>

// Problem constants
#define B_SZ 8
#define L_SZ 1024
#define DM 1024
#define NH 16
#define NG 4
#define HD 64
#define QKV_E 1536
#define MROWS (B_SZ * L_SZ)   // 8192

// ---------------- scratch (device globals; no allocation allowed) ----------
__device__ __half g_wqh[QKV_E * DM];
__device__ __half g_woh[DM * DM];
__device__ __half g_ah[MROWS * DM];              // attention output
__device__ __half g_qh[B_SZ * NH * L_SZ * HD];
__device__ __half g_kh[B_SZ * NG * L_SZ * HD];
__device__ __half g_vth[B_SZ * NG * HD * L_SZ];  // [b,g,d,l]

// ============================================================================
// helpers
// ============================================================================
__device__ __forceinline__ uint32_t smem_u32(const void* p) {
    uint32_t a;
    asm("{ .reg .u64 t; cvta.to.shared.u64 t, %1; cvt.u32.u64 %0, t; }"
        : "=r"(a) : "l"(p));
    return a;
}

__device__ __forceinline__ void ldsm4(uint32_t* r, uint32_t addr) {
    asm volatile("ldmatrix.sync.aligned.m8n8.x4.shared.b16 {%0,%1,%2,%3}, [%4];"
        : "=r"(r[0]), "=r"(r[1]), "=r"(r[2]), "=r"(r[3]) : "r"(addr));
}

__device__ __forceinline__ void mma_f16(float* d, const uint32_t* a,
                                        const uint32_t* b) {
    asm volatile(
        "mma.sync.aligned.m16n8k16.row.col.f32.f16.f16.f32 "
        "{%0,%1,%2,%3}, {%4,%5,%6,%7}, {%8,%9}, {%0,%1,%2,%3};"
        : "+f"(d[0]), "+f"(d[1]), "+f"(d[2]), "+f"(d[3])
        : "r"(a[0]), "r"(a[1]), "r"(a[2]), "r"(a[3]), "r"(b[0]), "r"(b[1]));
}

__device__ __forceinline__ uint32_t pack2h(float a, float b) {
    __half2 h = __floats2half2_rn(a, b);
    return *(uint32_t*)&h;
}

#define CP16(smem_addr, gptr) \
    asm volatile("cp.async.cg.shared.global [%0], [%1], 16;" :: "r"(smem_addr), "l"(gptr))
#define CP_COMMIT() asm volatile("cp.async.commit_group;" ::: "memory")
#define CP_WAIT1()  asm volatile("cp.async.wait_group 1;" ::: "memory")
#define CP_WAIT2()  asm volatile("cp.async.wait_group 2;" ::: "memory")

// ============================================================================
// Kernel 0: fp32 -> fp16 for the two weight matrices (one launch)
// ============================================================================
__global__ void __launch_bounds__(256) convert_w_kernel(
    const float* __restrict__ wq, __half* __restrict__ wqh, int n1,
    const float* __restrict__ wo, __half* __restrict__ woh, int n2)
{
    int i = blockIdx.x * blockDim.x + threadIdx.x;
    const float* src;
    __half* dst;
    if (i < n1)           { src = wq; dst = wqh; }
    else if (i < n1 + n2) { src = wo; dst = woh; i -= n1; }
    else return;
    float4 v0 = ((const float4*)src)[2 * i];
    float4 v1 = ((const float4*)src)[2 * i + 1];
    uint4 hi;
    hi.x = pack2h(v0.x, v0.y);
    hi.y = pack2h(v0.z, v0.w);
    hi.z = pack2h(v1.x, v1.y);
    hi.w = pack2h(v1.z, v1.w);
    ((uint4*)dst)[i] = hi;
}

// ============================================================================
// Kernel 1a: QKV GEMM with in-loader fp32->fp16 conversion of A (= x),
// + fused norm/RoPE/transpose epilogue.
// 128x128 CTA tile, BK=32, 8 warps (4m x 2n).
// 4-stage ring (A 8KB fp16 | B 8KB fp16 = 16KB/stage, 64KB total).
// A: LDG fp32 (chunk bk+3 prefetch) -> convert -> STS (chunk bk+2 slot).
// B: cp.async 3-deep.
// ============================================================================
#define PSTAGE 16384
#define QGEMM_SMEM (4 * PSTAGE)   // 64KB

__global__ void __launch_bounds__(256, 2) gemm_qkv_fused_kernel(
    const float* __restrict__ X, const __half* __restrict__ Bh,
    __half* __restrict__ qh, __half* __restrict__ kh, __half* __restrict__ vth)
{
    const int K = DM;
    extern __shared__ char smem[];
    const uint32_t sb = smem_u32(smem);
    const int tid = threadIdx.x;
    const int wid = tid >> 5;
    const int lane = tid & 31;
    const int m0 = blockIdx.y * 128;
    const int n0 = blockIdx.x * 128;
    const int NC = K >> 5;                  // 32

    const int warp_m = wid & 3;
    const int warp_n = wid >> 2;

    const int lrow = tid >> 1;
    const int swz_l = (lrow >> 1) & 3;
    const uint32_t so0 = lrow * 64 + ((((tid & 1) * 2 + 0) ^ swz_l) << 4);
    const uint32_t so1 = lrow * 64 + ((((tid & 1) * 2 + 1) ^ swz_l) << 4);
    const size_t roA0 = (size_t)(m0 + lrow) * K + (tid & 1) * 16;   // fp32 elems
    const size_t roB0 = (size_t)(n0 + lrow) * K + (tid & 1) * 16;   // fp16 elems

    float4 ra[4];
    auto ldgA = [&](int c) {
        const float* p = X + roA0 + c * 32;
        ra[0] = *(const float4*)(p);
        ra[1] = *(const float4*)(p + 4);
        ra[2] = *(const float4*)(p + 8);
        ra[3] = *(const float4*)(p + 12);
    };
    auto stsA = [&](int st) {
        uint4 u0 = make_uint4(pack2h(ra[0].x, ra[0].y), pack2h(ra[0].z, ra[0].w),
                              pack2h(ra[1].x, ra[1].y), pack2h(ra[1].z, ra[1].w));
        uint4 u1 = make_uint4(pack2h(ra[2].x, ra[2].y), pack2h(ra[2].z, ra[2].w),
                              pack2h(ra[3].x, ra[3].y), pack2h(ra[3].z, ra[3].w));
        *(uint4*)(smem + st * PSTAGE + so0) = u0;
        *(uint4*)(smem + st * PSTAGE + so1) = u1;
    };
    auto issueB = [&](int c, int st) {
        const uint32_t base = sb + st * PSTAGE + 8192;
        CP16(base + so0, Bh + roB0 + c * 32);
        CP16(base + so1, Bh + roB0 + c * 32 + 8);
    };

    uint32_t aoff[2][2];
#pragma unroll
    for (int tm = 0; tm < 2; tm++) {
        int r = warp_m * 32 + tm * 16 + (lane & 15);
        int sw = (r >> 1) & 3;
#pragma unroll
        for (int ks = 0; ks < 2; ks++) {
            int ch = ks * 2 + (lane >> 4);
            aoff[tm][ks] = r * 64 + ((ch ^ sw) << 4);
        }
    }
    uint32_t boff[4][2];
#pragma unroll
    for (int bp = 0; bp < 4; bp++) {
        int r = warp_n * 64 + bp * 16 + ((lane >> 4) << 3) + (lane & 7);
        int sw = (r >> 1) & 3;
#pragma unroll
        for (int ks = 0; ks < 2; ks++) {
            int ch = ks * 2 + ((lane >> 3) & 1);
            boff[bp][ks] = 8192 + r * 64 + ((ch ^ sw) << 4);
        }
    }

    float acc[2][8][4];
#pragma unroll
    for (int i = 0; i < 2; i++)
#pragma unroll
        for (int j = 0; j < 8; j++)
#pragma unroll
            for (int q = 0; q < 4; q++) acc[i][j][q] = 0.f;

    // prologue: A chunks 0,1 STS'd; chunk 2 staged in regs; B chunks 0..2 async
    ldgA(0); stsA(0); issueB(0, 0); CP_COMMIT();
    ldgA(1); stsA(1); issueB(1, 1); CP_COMMIT();
    ldgA(2); issueB(2, 2); CP_COMMIT();

#pragma unroll 1
    for (int bk = 0; bk < NC; bk++) {
        CP_WAIT2();                  // B chunk bk landed
        __syncthreads();             // A chunk bk (STS'd earlier) visible too
        if (bk + 2 < NC) stsA((bk + 2) & 3);   // regs hold chunk bk+2
        if (bk + 3 < NC) { ldgA(bk + 3); issueB(bk + 3, (bk + 3) & 3); }
        CP_COMMIT();

        const uint32_t stg = sb + (bk & 3) * PSTAGE;
#pragma unroll
        for (int ks = 0; ks < 2; ks++) {
            uint32_t fa[2][4];
#pragma unroll
            for (int tm = 0; tm < 2; tm++)
                ldsm4(fa[tm], stg + aoff[tm][ks]);
            uint32_t fb[8][2];
#pragma unroll
            for (int bp = 0; bp < 4; bp++) {
                uint32_t t[4];
                ldsm4(t, stg + boff[bp][ks]);
                fb[2*bp][0] = t[0]; fb[2*bp][1] = t[1];
                fb[2*bp+1][0] = t[2]; fb[2*bp+1][1] = t[3];
            }
#pragma unroll
            for (int tm = 0; tm < 2; tm++)
#pragma unroll
                for (int tn = 0; tn < 8; tn++)
                    mma_f16(acc[tm][tn], fa[tm], fb[tn]);
        }
    }

    // ---- FUSED epilogue: norm + rope + scatter fp16 ----
    const int er = lane >> 2;
    const int jb = lane & 3;              // j = tn*4 + jb
    const int slot = blockIdx.x * 2 + warp_n;

#pragma unroll
    for (int tm = 0; tm < 2; tm++) {
#pragma unroll
        for (int rr = 0; rr < 2; rr++) {
            const int m = m0 + warp_m * 32 + tm * 16 + er + rr * 8;
            const int b = m >> 10;
            const int l = m & 1023;
            const int q0 = 2 * rr, q1 = 2 * rr + 1;

            if (slot < 20) {
                float ss = 0.f;
#pragma unroll
                for (int tn = 0; tn < 8; tn++)
                    ss += acc[tm][tn][q0] * acc[tm][tn][q0]
                        + acc[tm][tn][q1] * acc[tm][tn][q1];
                ss += __shfl_xor_sync(0xffffffffu, ss, 1);
                ss += __shfl_xor_sync(0xffffffffu, ss, 2);
                float inv = 1.f / (sqrtf(ss) + 1e-10f);
                if (slot < 16) inv *= 0.18033688011112042f;  // 0.125*log2(e)

                const float psum = (float)((l >> 5) + (l & 31));
                __half* dst;
                if (slot < 16)
                    dst = qh + (((size_t)b * NH + slot) * L_SZ + l) * HD;
                else
                    dst = kh + (((size_t)b * NG + (slot - 16)) * L_SZ + l) * HD;
#pragma unroll
                for (int tn = 0; tn < 8; tn++) {
                    const int j = tn * 4 + jb;
                    const float fr = psum * exp2f(-0.41524101186098287f * (float)j);
                    float s, c;
                    sincosf(fr, &s, &c);
                    const float x1 = acc[tm][tn][q0] * inv;
                    const float x2 = acc[tm][tn][q1] * inv;
                    dst[j]      = __float2half_rn(x1 * c - x2 * s);
                    dst[j + 32] = __float2half_rn(x1 * s + x2 * c);
                }
            } else {
                __half* dst = vth + ((size_t)(b * NG + slot - 20) * HD) * L_SZ + l;
                const int ec = jb * 2;
#pragma unroll
                for (int tn = 0; tn < 8; tn++) {
                    const int d0 = tn * 8 + ec;
                    dst[(size_t)d0 * L_SZ]       = __float2half_rn(acc[tm][tn][q0]);
                    dst[(size_t)(d0 + 1) * L_SZ] = __float2half_rn(acc[tm][tn][q1]);
                }
            }
        }
    }
}

// ============================================================================
// Kernel 1b: plain GEMM (out-projection), R13 pair-scheme verbatim.
// 6-stage ring = 3 pair-slots, 2 pairs in flight.
// ============================================================================
#define OSTAGE 16384
#define OGEMM_SMEM (6 * OSTAGE)   // 96KB

__global__ void __launch_bounds__(256, 2) gemm_f16_kernel(
    const __half* __restrict__ Ah, const __half* __restrict__ Bh,
    float* __restrict__ C, int N, int K)
{
    extern __shared__ char smem[];
    const uint32_t sb = smem_u32(smem);
    const int tid = threadIdx.x;
    const int wid = tid >> 5;
    const int lane = tid & 31;
    const int m0 = blockIdx.y * 128;
    const int n0 = blockIdx.x * 128;
    const int NP = K >> 6;

    const int warp_m = wid & 3;
    const int warp_n = wid >> 2;

    const int lrow = tid >> 1;
    const int swz_l = (lrow >> 1) & 3;
    const uint32_t so0 = lrow * 64 + ((((tid & 1) * 2 + 0) ^ swz_l) << 4);
    const uint32_t so1 = lrow * 64 + ((((tid & 1) * 2 + 1) ^ swz_l) << 4);
    const size_t roA0 = (size_t)(m0 + lrow) * K + (tid & 1) * 16;
    const size_t roB0 = (size_t)(n0 + lrow) * K + (tid & 1) * 16;

    auto issue_pair = [&](int p, int slot) {
        const uint32_t base = sb + slot * 2 * OSTAGE;
#pragma unroll
        for (int half = 0; half < 2; half++) {
            const uint32_t hb = base + half * OSTAGE;
            const size_t ra = roA0 + (2 * p + half) * 32;
            const size_t rb = roB0 + (2 * p + half) * 32;
            CP16(hb + so0,        Ah + ra);
            CP16(hb + so1,        Ah + ra + 8);
            CP16(hb + 8192 + so0, Bh + rb);
            CP16(hb + 8192 + so1, Bh + rb + 8);
        }
    };

    uint32_t aoff[2][2];
#pragma unroll
    for (int tm = 0; tm < 2; tm++) {
        int r = warp_m * 32 + tm * 16 + (lane & 15);
        int sw = (r >> 1) & 3;
#pragma unroll
        for (int ks = 0; ks < 2; ks++) {
            int ch = ks * 2 + (lane >> 4);
            aoff[tm][ks] = r * 64 + ((ch ^ sw) << 4);
        }
    }
    uint32_t boff[4][2];
#pragma unroll
    for (int bp = 0; bp < 4; bp++) {
        int r = warp_n * 64 + bp * 16 + ((lane >> 4) << 3) + (lane & 7);
        int sw = (r >> 1) & 3;
#pragma unroll
        for (int ks = 0; ks < 2; ks++) {
            int ch = ks * 2 + ((lane >> 3) & 1);
            boff[bp][ks] = r * 64 + ((ch ^ sw) << 4);
        }
    }

    float acc[2][8][4];
#pragma unroll
    for (int i = 0; i < 2; i++)
#pragma unroll
        for (int j = 0; j < 8; j++)
#pragma unroll
            for (int q = 0; q < 4; q++) acc[i][j][q] = 0.f;

    issue_pair(0, 0); CP_COMMIT();
    issue_pair(1, 1); CP_COMMIT();

    int slot = 0;
#pragma unroll 1
    for (int p = 0; p < NP; p++) {
        CP_WAIT1();
        __syncthreads();
        {
            const int pn = p + 2;
            if (pn < NP) {
                int sl = slot + 2; if (sl >= 3) sl -= 3;
                issue_pair(pn, sl);
            }
        }
        CP_COMMIT();

        const uint32_t pb = sb + slot * 2 * OSTAGE;
#pragma unroll
        for (int half = 0; half < 2; half++) {
            const uint32_t ah = pb + half * OSTAGE;
            const uint32_t wh = ah + 8192;
#pragma unroll
            for (int ks = 0; ks < 2; ks++) {
                uint32_t fa[2][4];
#pragma unroll
                for (int tm = 0; tm < 2; tm++)
                    ldsm4(fa[tm], ah + aoff[tm][ks]);
                uint32_t fb[8][2];
#pragma unroll
                for (int bp = 0; bp < 4; bp++) {
                    uint32_t t[4];
                    ldsm4(t, wh + boff[bp][ks]);
                    fb[2*bp][0] = t[0]; fb[2*bp][1] = t[1];
                    fb[2*bp+1][0] = t[2]; fb[2*bp+1][1] = t[3];
                }
#pragma unroll
                for (int tm = 0; tm < 2; tm++)
#pragma unroll
                    for (int tn = 0; tn < 8; tn++)
                        mma_f16(acc[tm][tn], fa[tm], fb[tn]);
            }
        }
        slot = (slot == 2) ? 0 : slot + 1;
    }

    const int er = lane >> 2;
    const int ec = (lane & 3) * 2;
#pragma unroll
    for (int tm = 0; tm < 2; tm++) {
        const int rbase = m0 + warp_m * 32 + tm * 16 + er;
#pragma unroll
        for (int tn = 0; tn < 8; tn++) {
            const int cbase = n0 + warp_n * 64 + tn * 8 + ec;
            float* p0 = C + (size_t)rbase * N + cbase;
            float* p1 = C + (size_t)(rbase + 8) * N + cbase;
            *(float2*)p0 = make_float2(acc[tm][tn][0], acc[tm][tn][1]);
            *(float2*)p1 = make_float2(acc[tm][tn][2], acc[tm][tn][3]);
        }
    }
}

// ============================================================================
// Kernel 2: tensor-core flash attention (R12/13 verbatim).
// ============================================================================
#define A_OFF_QH 0
#define A_OFF_KV 16384
#define A_STAGE  16384
#define ATTN_SMEM (A_OFF_KV + 3 * A_STAGE)   // 65536

__global__ void __launch_bounds__(256, 2) attn_f16_kernel(
    const __half* __restrict__ qh, const __half* __restrict__ kh,
    const __half* __restrict__ vth,
    __half* __restrict__ Oh)
{
    extern __shared__ char smem[];
    const uint32_t sb = smem_u32(smem);
    const int tid = threadIdx.x;
    const int wid = tid >> 5;
    const int lane = tid & 31;

    const int qt = blockIdx.x;
    const int h = blockIdx.y;
    const int b = blockIdx.z;
    const int g = h >> 2;

    const __half* Qh_g = qh + ((((size_t)b * NH + h) * L_SZ) + qt * 128) * HD;
    const __half* Kh_g = kh + (((size_t)b * NG + g) * L_SZ) * HD;
    const __half* Vth_g = vth + ((size_t)b * NG + g) * HD * L_SZ;

#pragma unroll
    for (int i = 0; i < 4; i++) {
        int idx = tid * 4 + i;
        int row = idx >> 3, ch = idx & 7;
        uint32_t sw = (uint32_t)(row * 128 + ((ch ^ (row & 7)) << 4));
        CP16(sb + A_OFF_QH + sw, Qh_g + row * 64 + ch * 8);
    }

    auto issue_chunk = [&](int c, int st) {
        const uint32_t base = sb + A_OFF_KV + st * A_STAGE;
#pragma unroll
        for (int i = 0; i < 2; i++) {
            int idx = tid * 2 + i;
            int row = idx >> 3, ch = idx & 7;
            uint32_t sw = (uint32_t)(row * 128 + ((ch ^ (row & 7)) << 4));
            CP16(base + sw,        Kh_g + (size_t)(c * 64 + row) * 64 + ch * 8);
            CP16(base + 8192 + sw, Vth_g + (size_t)row * L_SZ + c * 64 + ch * 8);
        }
    };

    issue_chunk(0, 0);
    CP_COMMIT();
    issue_chunk(1, 1);
    CP_COMMIT();

    uint32_t qoff[4];
#pragma unroll
    for (int ks = 0; ks < 4; ks++) {
        int r = wid * 16 + (lane & 15);
        int ch = ks * 2 + (lane >> 4);
        qoff[ks] = (uint32_t)(r * 128 + ((ch ^ (r & 7)) << 4));
    }
    uint32_t lbo[4][4];
#pragma unroll
    for (int np = 0; np < 4; np++) {
        int r = np * 16 + ((lane >> 4) << 3) + (lane & 7);
#pragma unroll
        for (int ks = 0; ks < 4; ks++) {
            int ch = ks * 2 + ((lane >> 3) & 1);
            lbo[np][ks] = (uint32_t)(r * 128 + ((ch ^ (r & 7)) << 4));
        }
    }

    uint32_t qfh[4][4];
    float oacc[8][4];
#pragma unroll
    for (int t = 0; t < 8; t++)
#pragma unroll
        for (int q = 0; q < 4; q++) oacc[t][q] = 0.f;
    float mrow[2] = {-INFINITY, -INFINITY};
    float lrow[2] = {0.f, 0.f};

    int st = 0;
#pragma unroll 1
    for (int c = 0; c < 16; c++) {
        CP_WAIT1();
        __syncthreads();
        {
            const int cn = c + 2;
            if (cn < 16) {
                int stn = st + 2; if (stn >= 3) stn -= 3;
                issue_chunk(cn, stn);
            }
        }
        CP_COMMIT();

        if (c == 0) {
#pragma unroll
            for (int ks = 0; ks < 4; ks++)
                ldsm4(qfh[ks], sb + A_OFF_QH + qoff[ks]);
        }

        const uint32_t kb = sb + A_OFF_KV + st * A_STAGE;
        const uint32_t vbh = kb + 8192;

        float sacc[8][4];
#pragma unroll
        for (int t = 0; t < 8; t++)
#pragma unroll
            for (int q = 0; q < 4; q++) sacc[t][q] = 0.f;
#pragma unroll
        for (int ks = 0; ks < 4; ks++) {
            uint32_t kth[4][4];
#pragma unroll
            for (int np = 0; np < 4; np++)
                ldsm4(kth[np], kb + lbo[np][ks]);
#pragma unroll
            for (int np = 0; np < 4; np++) {
                mma_f16(sacc[2*np],   qfh[ks], kth[np]);
                mma_f16(sacc[2*np+1], qfh[ks], kth[np] + 2);
            }
        }

#pragma unroll
        for (int r = 0; r < 2; r++) {
            float mx = mrow[r];
#pragma unroll
            for (int t = 0; t < 8; t++)
                mx = fmaxf(mx, fmaxf(sacc[t][2*r], sacc[t][2*r+1]));
            mx = fmaxf(mx, __shfl_xor_sync(0xffffffffu, mx, 1));
            mx = fmaxf(mx, __shfl_xor_sync(0xffffffffu, mx, 2));
            const float sc = exp2f(mrow[r] - mx);
            mrow[r] = mx;
            float sum = 0.f;
#pragma unroll
            for (int t = 0; t < 8; t++) {
                float p0 = exp2f(sacc[t][2*r]   - mx);
                float p1 = exp2f(sacc[t][2*r+1] - mx);
                sacc[t][2*r] = p0; sacc[t][2*r+1] = p1;
                sum += p0 + p1;
            }
            sum += __shfl_xor_sync(0xffffffffu, sum, 1);
            sum += __shfl_xor_sync(0xffffffffu, sum, 2);
            lrow[r] = lrow[r] * sc + sum;
#pragma unroll
            for (int t = 0; t < 8; t++) {
                oacc[t][2*r] *= sc; oacc[t][2*r+1] *= sc;
            }
        }

#pragma unroll
        for (int j = 0; j < 4; j++) {
            uint32_t pah[4];
            pah[0] = pack2h(sacc[2*j][0],   sacc[2*j][1]);
            pah[1] = pack2h(sacc[2*j][2],   sacc[2*j][3]);
            pah[2] = pack2h(sacc[2*j+1][0], sacc[2*j+1][1]);
            pah[3] = pack2h(sacc[2*j+1][2], sacc[2*j+1][3]);
            uint32_t vfh[4][4];
#pragma unroll
            for (int dp = 0; dp < 4; dp++)
                ldsm4(vfh[dp], vbh + lbo[dp][j]);
#pragma unroll
            for (int dp = 0; dp < 4; dp++) {
                mma_f16(oacc[2*dp],   pah, vfh[dp]);
                mma_f16(oacc[2*dp+1], pah, vfh[dp] + 2);
            }
        }

        st = (st == 2) ? 0 : st + 1;
    }

    const float inv0 = 1.f / lrow[0];
    const float inv1 = 1.f / lrow[1];
    const int q0 = qt * 128 + wid * 16 + (lane >> 2);
#pragma unroll
    for (int t = 0; t < 8; t++) {
        const int col = h * 64 + t * 8 + (lane & 3) * 2;
        const size_t o0 = ((size_t)(b * L_SZ + q0)) * DM + col;
        const size_t o1 = ((size_t)(b * L_SZ + q0 + 8)) * DM + col;
        *(uint32_t*)(Oh + o0) = pack2h(oacc[t][0] * inv0, oacc[t][1] * inv0);
        *(uint32_t*)(Oh + o1) = pack2h(oacc[t][2] * inv1, oacc[t][3] * inv1);
    }
}

// ============================================================================
// launch
// ============================================================================
extern "C" void kernel_launch(void* const* d_in, const int* in_sizes, int n_in,
                              void* d_out, int out_size)
{
    const float* x     = (const float*)d_in[0];
    const float* w_qkv = (const float*)d_in[1];
    const float* w_o   = (const float*)d_in[2];
    float* out = (float*)d_out;

    __half *wqh_p, *woh_p, *ah_p;
    __half *qh_p, *kh_p, *vth_p;
    cudaGetSymbolAddress((void**)&wqh_p, g_wqh);
    cudaGetSymbolAddress((void**)&woh_p, g_woh);
    cudaGetSymbolAddress((void**)&ah_p,  g_ah);
    cudaGetSymbolAddress((void**)&qh_p,  g_qh);
    cudaGetSymbolAddress((void**)&kh_p,  g_kh);
    cudaGetSymbolAddress((void**)&vth_p, g_vth);

    cudaFuncSetAttribute(gemm_qkv_fused_kernel,
                         cudaFuncAttributeMaxDynamicSharedMemorySize, QGEMM_SMEM);
    cudaFuncSetAttribute(gemm_f16_kernel,
                         cudaFuncAttributeMaxDynamicSharedMemorySize, OGEMM_SMEM);
    cudaFuncSetAttribute(attn_f16_kernel,
                         cudaFuncAttributeMaxDynamicSharedMemorySize, ATTN_SMEM);

    // 0) convert weights only (x converted inside the QKV GEMM loader)
    {
        const int n1 = QKV_E * DM / 8, n2 = DM * DM / 8;
        convert_w_kernel<<<(n1 + n2 + 255) / 256, 256>>>(w_qkv, wqh_p, n1,
                                                         w_o, woh_p, n2);
    }
    // 1) QKV projection (fp32 A in-loader convert) + fused norm/rope/transpose
    {
        dim3 grid(QKV_E / 128, MROWS / 128);
        gemm_qkv_fused_kernel<<<grid, 256, QGEMM_SMEM>>>(x, wqh_p,
                                                         qh_p, kh_p, vth_p);
    }
    // 2) attention
    {
        dim3 grid(L_SZ / 128, NH, B_SZ);
        attn_f16_kernel<<<grid, 256, ATTN_SMEM>>>(qh_p, kh_p, vth_p, ah_p);
    }
    // 3) output projection
    {
        dim3 grid(DM / 128, MROWS / 128);
        gemm_f16_kernel<<<grid, 256, OGEMM_SMEM>>>(ah_p, woh_p, out, DM, DM);
    }
}

// round 16
// speedup vs baseline: 1.0610x; 1.0610x over previous
#include <cuda_runtime.h>
#include <cuda_fp16.h>
#include <math.h>
#include <stdint.h>

// Problem constants
#define B_SZ 8
#define L_SZ 1024
#define DM 1024
#define NH 16
#define NG 4
#define HD 64
#define QKV_E 1536
#define MROWS (B_SZ * L_SZ)   // 8192

// ---------------- scratch (device globals; no allocation allowed) ----------
__device__ __half g_xh[MROWS * DM];
__device__ __half g_wqh[QKV_E * DM];
__device__ __half g_woh[DM * DM];
__device__ __half g_ah[MROWS * DM];              // attention output
__device__ __half g_qh[B_SZ * NH * L_SZ * HD];
__device__ __half g_kh[B_SZ * NG * L_SZ * HD];
__device__ __half g_vth[B_SZ * NG * HD * L_SZ];  // [b,g,d,l]

// ============================================================================
// helpers
// ============================================================================
__device__ __forceinline__ uint32_t smem_u32(const void* p) {
    uint32_t a;
    asm("{ .reg .u64 t; cvta.to.shared.u64 t, %1; cvt.u32.u64 %0, t; }"
        : "=r"(a) : "l"(p));
    return a;
}

__device__ __forceinline__ void ldsm4(uint32_t* r, uint32_t addr) {
    asm volatile("ldmatrix.sync.aligned.m8n8.x4.shared.b16 {%0,%1,%2,%3}, [%4];"
        : "=r"(r[0]), "=r"(r[1]), "=r"(r[2]), "=r"(r[3]) : "r"(addr));
}

__device__ __forceinline__ void mma_f16(float* d, const uint32_t* a,
                                        const uint32_t* b) {
    asm volatile(
        "mma.sync.aligned.m16n8k16.row.col.f32.f16.f16.f32 "
        "{%0,%1,%2,%3}, {%4,%5,%6,%7}, {%8,%9}, {%0,%1,%2,%3};"
        : "+f"(d[0]), "+f"(d[1]), "+f"(d[2]), "+f"(d[3])
        : "r"(a[0]), "r"(a[1]), "r"(a[2]), "r"(a[3]), "r"(b[0]), "r"(b[1]));
}

__device__ __forceinline__ uint32_t pack2h(float a, float b) {
    __half2 h = __floats2half2_rn(a, b);
    return *(uint32_t*)&h;
}

#define CP16(smem_addr, gptr) \
    asm volatile("cp.async.cg.shared.global [%0], [%1], 16;" :: "r"(smem_addr), "l"(gptr))
#define CP_COMMIT() asm volatile("cp.async.commit_group;" ::: "memory")
#define CP_WAIT1()  asm volatile("cp.async.wait_group 1;" ::: "memory")

// ============================================================================
// Kernel 0: fp32 -> fp16, all three operands in ONE launch
// ============================================================================
__global__ void __launch_bounds__(256) convert_all_kernel(
    const float* __restrict__ x, __half* __restrict__ xh, int n1,
    const float* __restrict__ wq, __half* __restrict__ wqh, int n2,
    const float* __restrict__ wo, __half* __restrict__ woh, int n3)
{
    int i = blockIdx.x * blockDim.x + threadIdx.x;
    const float* src;
    __half* dst;
    if (i < n1)                { src = x;  dst = xh; }
    else if (i < n1 + n2)      { src = wq; dst = wqh; i -= n1; }
    else if (i < n1 + n2 + n3) { src = wo; dst = woh; i -= n1 + n2; }
    else return;
    float4 v0 = ((const float4*)src)[2 * i];
    float4 v1 = ((const float4*)src)[2 * i + 1];
    uint4 hi;
    hi.x = pack2h(v0.x, v0.y);
    hi.y = pack2h(v0.z, v0.w);
    hi.z = pack2h(v1.x, v1.y);
    hi.w = pack2h(v1.z, v1.w);
    ((uint4*)dst)[i] = hi;
}

// ============================================================================
// GEMM: 128x128 CTA, BK=32 chunks processed in PAIRS (64 K per sync).
// 6-stage ring = 3 pair-slots, 2 pairs in flight, ONE sync per 64 HMMAs.
// Stage = Ah | Bh, each 128x32 fp16 (64B rows, chunk-XOR swizzle) = 16KB.
// ============================================================================
#define PSTAGE 16384
#define PGEMM_SMEM (6 * PSTAGE)   // 96KB

// ============================================================================
// Kernel 1a: QKV GEMM + fused norm/RoPE/transpose epilogue.
// ============================================================================
__global__ void __launch_bounds__(256, 2) gemm_qkv_fused_kernel(
    const __half* __restrict__ Ah, const __half* __restrict__ Bh,
    __half* __restrict__ qh, __half* __restrict__ kh, __half* __restrict__ vth)
{
    const int K = DM;
    extern __shared__ char smem[];
    const uint32_t sb = smem_u32(smem);
    const int tid = threadIdx.x;
    const int wid = tid >> 5;
    const int lane = tid & 31;
    const int m0 = blockIdx.y * 128;
    const int n0 = blockIdx.x * 128;
    const int NP = K >> 6;                  // 16 pair-iterations

    const int warp_m = wid & 3;
    const int warp_n = wid >> 2;

    const int lrow = tid >> 1;
    const int swz_l = (lrow >> 1) & 3;
    const uint32_t so0 = lrow * 64 + ((((tid & 1) * 2 + 0) ^ swz_l) << 4);
    const uint32_t so1 = lrow * 64 + ((((tid & 1) * 2 + 1) ^ swz_l) << 4);
    const size_t roA0 = (size_t)(m0 + lrow) * K + (tid & 1) * 16;
    const size_t roB0 = (size_t)(n0 + lrow) * K + (tid & 1) * 16;

    auto issue_pair = [&](int p, int slot) {
        const uint32_t base = sb + slot * 2 * PSTAGE;
#pragma unroll
        for (int half = 0; half < 2; half++) {
            const uint32_t hb = base + half * PSTAGE;
            const size_t ra = roA0 + (2 * p + half) * 32;
            const size_t rb = roB0 + (2 * p + half) * 32;
            CP16(hb + so0,        Ah + ra);
            CP16(hb + so1,        Ah + ra + 8);
            CP16(hb + 8192 + so0, Bh + rb);
            CP16(hb + 8192 + so1, Bh + rb + 8);
        }
    };

    uint32_t aoff[2][2];
#pragma unroll
    for (int tm = 0; tm < 2; tm++) {
        int r = warp_m * 32 + tm * 16 + (lane & 15);
        int sw = (r >> 1) & 3;
#pragma unroll
        for (int ks = 0; ks < 2; ks++) {
            int ch = ks * 2 + (lane >> 4);
            aoff[tm][ks] = r * 64 + ((ch ^ sw) << 4);
        }
    }
    uint32_t boff[4][2];
#pragma unroll
    for (int bp = 0; bp < 4; bp++) {
        int r = warp_n * 64 + bp * 16 + ((lane >> 4) << 3) + (lane & 7);
        int sw = (r >> 1) & 3;
#pragma unroll
        for (int ks = 0; ks < 2; ks++) {
            int ch = ks * 2 + ((lane >> 3) & 1);
            boff[bp][ks] = r * 64 + ((ch ^ sw) << 4);
        }
    }

    float acc[2][8][4];
#pragma unroll
    for (int i = 0; i < 2; i++)
#pragma unroll
        for (int j = 0; j < 8; j++)
#pragma unroll
            for (int q = 0; q < 4; q++) acc[i][j][q] = 0.f;

    issue_pair(0, 0); CP_COMMIT();
    issue_pair(1, 1); CP_COMMIT();

    int slot = 0;
#pragma unroll 1
    for (int p = 0; p < NP; p++) {
        CP_WAIT1();              // pair p landed
        __syncthreads();
        {
            const int pn = p + 2;
            if (pn < NP) {
                int sl = slot + 2; if (sl >= 3) sl -= 3;
                issue_pair(pn, sl);
            }
        }
        CP_COMMIT();

        const uint32_t pb = sb + slot * 2 * PSTAGE;
#pragma unroll
        for (int half = 0; half < 2; half++) {
            const uint32_t ah = pb + half * PSTAGE;
            const uint32_t wh = ah + 8192;
#pragma unroll
            for (int ks = 0; ks < 2; ks++) {
                uint32_t fa[2][4];
#pragma unroll
                for (int tm = 0; tm < 2; tm++)
                    ldsm4(fa[tm], ah + aoff[tm][ks]);
                uint32_t fb[8][2];
#pragma unroll
                for (int bp = 0; bp < 4; bp++) {
                    uint32_t t[4];
                    ldsm4(t, wh + boff[bp][ks]);
                    fb[2*bp][0] = t[0]; fb[2*bp][1] = t[1];
                    fb[2*bp+1][0] = t[2]; fb[2*bp+1][1] = t[3];
                }
#pragma unroll
                for (int tm = 0; tm < 2; tm++)
#pragma unroll
                    for (int tn = 0; tn < 8; tn++)
                        mma_f16(acc[tm][tn], fa[tm], fb[tn]);
            }
        }
        slot = (slot == 2) ? 0 : slot + 1;
    }

    // ---- FUSED epilogue: norm + rope + scatter fp16 ----
    const int er = lane >> 2;
    const int jb = lane & 3;              // j = tn*4 + jb
    const int slot_h = blockIdx.x * 2 + warp_n;

    // invfreq depends only on j = tn*4 + jb (thread-invariant across tm/rr)
    float invf[8];
#pragma unroll
    for (int tn = 0; tn < 8; tn++)
        invf[tn] = exp2f(-0.41524101186098287f * (float)(tn * 4 + jb));

#pragma unroll
    for (int tm = 0; tm < 2; tm++) {
#pragma unroll
        for (int rr = 0; rr < 2; rr++) {
            const int m = m0 + warp_m * 32 + tm * 16 + er + rr * 8;
            const int b = m >> 10;
            const int l = m & 1023;
            const int q0 = 2 * rr, q1 = 2 * rr + 1;

            if (slot_h < 20) {
                float ss = 0.f;
#pragma unroll
                for (int tn = 0; tn < 8; tn++)
                    ss += acc[tm][tn][q0] * acc[tm][tn][q0]
                        + acc[tm][tn][q1] * acc[tm][tn][q1];
                ss += __shfl_xor_sync(0xffffffffu, ss, 1);
                ss += __shfl_xor_sync(0xffffffffu, ss, 2);
                float inv = 1.f / (sqrtf(ss) + 1e-10f);
                if (slot_h < 16) inv *= 0.18033688011112042f;  // 0.125*log2(e)

                const float psum = (float)((l >> 5) + (l & 31));
                __half* dst;
                if (slot_h < 16)
                    dst = qh + (((size_t)b * NH + slot_h) * L_SZ + l) * HD;
                else
                    dst = kh + (((size_t)b * NG + (slot_h - 16)) * L_SZ + l) * HD;
#pragma unroll
                for (int tn = 0; tn < 8; tn++) {
                    const int j = tn * 4 + jb;
                    const float fr = psum * invf[tn];
                    float s, c;
                    __sincosf(fr, &s, &c);
                    const float x1 = acc[tm][tn][q0] * inv;
                    const float x2 = acc[tm][tn][q1] * inv;
                    dst[j]      = __float2half_rn(x1 * c - x2 * s);
                    dst[j + 32] = __float2half_rn(x1 * s + x2 * c);
                }
            } else {
                __half* dst = vth + ((size_t)(b * NG + slot_h - 20) * HD) * L_SZ + l;
                const int ec = jb * 2;
#pragma unroll
                for (int tn = 0; tn < 8; tn++) {
                    const int d0 = tn * 8 + ec;
                    dst[(size_t)d0 * L_SZ]       = __float2half_rn(acc[tm][tn][q0]);
                    dst[(size_t)(d0 + 1) * L_SZ] = __float2half_rn(acc[tm][tn][q1]);
                }
            }
        }
    }
}

// ============================================================================
// Kernel 1b: plain GEMM (out-projection): C fp32 = A[M,K] @ B[N,K]^T
// ============================================================================
__global__ void __launch_bounds__(256, 2) gemm_f16_kernel(
    const __half* __restrict__ Ah, const __half* __restrict__ Bh,
    float* __restrict__ C, int N, int K)
{
    extern __shared__ char smem[];
    const uint32_t sb = smem_u32(smem);
    const int tid = threadIdx.x;
    const int wid = tid >> 5;
    const int lane = tid & 31;
    const int m0 = blockIdx.y * 128;
    const int n0 = blockIdx.x * 128;
    const int NP = K >> 6;

    const int warp_m = wid & 3;
    const int warp_n = wid >> 2;

    const int lrow = tid >> 1;
    const int swz_l = (lrow >> 1) & 3;
    const uint32_t so0 = lrow * 64 + ((((tid & 1) * 2 + 0) ^ swz_l) << 4);
    const uint32_t so1 = lrow * 64 + ((((tid & 1) * 2 + 1) ^ swz_l) << 4);
    const size_t roA0 = (size_t)(m0 + lrow) * K + (tid & 1) * 16;
    const size_t roB0 = (size_t)(n0 + lrow) * K + (tid & 1) * 16;

    auto issue_pair = [&](int p, int slot) {
        const uint32_t base = sb + slot * 2 * PSTAGE;
#pragma unroll
        for (int half = 0; half < 2; half++) {
            const uint32_t hb = base + half * PSTAGE;
            const size_t ra = roA0 + (2 * p + half) * 32;
            const size_t rb = roB0 + (2 * p + half) * 32;
            CP16(hb + so0,        Ah + ra);
            CP16(hb + so1,        Ah + ra + 8);
            CP16(hb + 8192 + so0, Bh + rb);
            CP16(hb + 8192 + so1, Bh + rb + 8);
        }
    };

    uint32_t aoff[2][2];
#pragma unroll
    for (int tm = 0; tm < 2; tm++) {
        int r = warp_m * 32 + tm * 16 + (lane & 15);
        int sw = (r >> 1) & 3;
#pragma unroll
        for (int ks = 0; ks < 2; ks++) {
            int ch = ks * 2 + (lane >> 4);
            aoff[tm][ks] = r * 64 + ((ch ^ sw) << 4);
        }
    }
    uint32_t boff[4][2];
#pragma unroll
    for (int bp = 0; bp < 4; bp++) {
        int r = warp_n * 64 + bp * 16 + ((lane >> 4) << 3) + (lane & 7);
        int sw = (r >> 1) & 3;
#pragma unroll
        for (int ks = 0; ks < 2; ks++) {
            int ch = ks * 2 + ((lane >> 3) & 1);
            boff[bp][ks] = r * 64 + ((ch ^ sw) << 4);
        }
    }

    float acc[2][8][4];
#pragma unroll
    for (int i = 0; i < 2; i++)
#pragma unroll
        for (int j = 0; j < 8; j++)
#pragma unroll
            for (int q = 0; q < 4; q++) acc[i][j][q] = 0.f;

    issue_pair(0, 0); CP_COMMIT();
    issue_pair(1, 1); CP_COMMIT();

    int slot = 0;
#pragma unroll 1
    for (int p = 0; p < NP; p++) {
        CP_WAIT1();
        __syncthreads();
        {
            const int pn = p + 2;
            if (pn < NP) {
                int sl = slot + 2; if (sl >= 3) sl -= 3;
                issue_pair(pn, sl);
            }
        }
        CP_COMMIT();

        const uint32_t pb = sb + slot * 2 * PSTAGE;
#pragma unroll
        for (int half = 0; half < 2; half++) {
            const uint32_t ah = pb + half * PSTAGE;
            const uint32_t wh = ah + 8192;
#pragma unroll
            for (int ks = 0; ks < 2; ks++) {
                uint32_t fa[2][4];
#pragma unroll
                for (int tm = 0; tm < 2; tm++)
                    ldsm4(fa[tm], ah + aoff[tm][ks]);
                uint32_t fb[8][2];
#pragma unroll
                for (int bp = 0; bp < 4; bp++) {
                    uint32_t t[4];
                    ldsm4(t, wh + boff[bp][ks]);
                    fb[2*bp][0] = t[0]; fb[2*bp][1] = t[1];
                    fb[2*bp+1][0] = t[2]; fb[2*bp+1][1] = t[3];
                }
#pragma unroll
                for (int tm = 0; tm < 2; tm++)
#pragma unroll
                    for (int tn = 0; tn < 8; tn++)
                        mma_f16(acc[tm][tn], fa[tm], fb[tn]);
            }
        }
        slot = (slot == 2) ? 0 : slot + 1;
    }

    const int er = lane >> 2;
    const int ec = (lane & 3) * 2;
#pragma unroll
    for (int tm = 0; tm < 2; tm++) {
        const int rbase = m0 + warp_m * 32 + tm * 16 + er;
#pragma unroll
        for (int tn = 0; tn < 8; tn++) {
            const int cbase = n0 + warp_n * 64 + tn * 8 + ec;
            float* p0 = C + (size_t)rbase * N + cbase;
            float* p1 = C + (size_t)(rbase + 8) * N + cbase;
            *(float2*)p0 = make_float2(acc[tm][tn][0], acc[tm][tn][1]);
            *(float2*)p1 = make_float2(acc[tm][tn][2], acc[tm][tn][3]);
        }
    }
}

// ============================================================================
// Kernel 2: tensor-core flash attention (R12/13 verbatim).
// KV ring: 3 stages, 2 chunks in flight, ONE sync per chunk.
// ============================================================================
#define A_OFF_QH 0
#define A_OFF_KV 16384
#define A_STAGE  16384
#define ATTN_SMEM (A_OFF_KV + 3 * A_STAGE)   // 65536

__global__ void __launch_bounds__(256, 2) attn_f16_kernel(
    const __half* __restrict__ qh, const __half* __restrict__ kh,
    const __half* __restrict__ vth,
    __half* __restrict__ Oh)
{
    extern __shared__ char smem[];
    const uint32_t sb = smem_u32(smem);
    const int tid = threadIdx.x;
    const int wid = tid >> 5;
    const int lane = tid & 31;

    const int qt = blockIdx.x;
    const int h = blockIdx.y;
    const int b = blockIdx.z;
    const int g = h >> 2;

    const __half* Qh_g = qh + ((((size_t)b * NH + h) * L_SZ) + qt * 128) * HD;
    const __half* Kh_g = kh + (((size_t)b * NG + g) * L_SZ) * HD;
    const __half* Vth_g = vth + ((size_t)b * NG + g) * HD * L_SZ;

#pragma unroll
    for (int i = 0; i < 4; i++) {
        int idx = tid * 4 + i;
        int row = idx >> 3, ch = idx & 7;
        uint32_t sw = (uint32_t)(row * 128 + ((ch ^ (row & 7)) << 4));
        CP16(sb + A_OFF_QH + sw, Qh_g + row * 64 + ch * 8);
    }

    auto issue_chunk = [&](int c, int st) {
        const uint32_t base = sb + A_OFF_KV + st * A_STAGE;
#pragma unroll
        for (int i = 0; i < 2; i++) {
            int idx = tid * 2 + i;
            int row = idx >> 3, ch = idx & 7;
            uint32_t sw = (uint32_t)(row * 128 + ((ch ^ (row & 7)) << 4));
            CP16(base + sw,        Kh_g + (size_t)(c * 64 + row) * 64 + ch * 8);
            CP16(base + 8192 + sw, Vth_g + (size_t)row * L_SZ + c * 64 + ch * 8);
        }
    };

    issue_chunk(0, 0);
    CP_COMMIT();
    issue_chunk(1, 1);
    CP_COMMIT();

    uint32_t qoff[4];
#pragma unroll
    for (int ks = 0; ks < 4; ks++) {
        int r = wid * 16 + (lane & 15);
        int ch = ks * 2 + (lane >> 4);
        qoff[ks] = (uint32_t)(r * 128 + ((ch ^ (r & 7)) << 4));
    }
    uint32_t lbo[4][4];
#pragma unroll
    for (int np = 0; np < 4; np++) {
        int r = np * 16 + ((lane >> 4) << 3) + (lane & 7);
#pragma unroll
        for (int ks = 0; ks < 4; ks++) {
            int ch = ks * 2 + ((lane >> 3) & 1);
            lbo[np][ks] = (uint32_t)(r * 128 + ((ch ^ (r & 7)) << 4));
        }
    }

    uint32_t qfh[4][4];
    float oacc[8][4];
#pragma unroll
    for (int t = 0; t < 8; t++)
#pragma unroll
        for (int q = 0; q < 4; q++) oacc[t][q] = 0.f;
    float mrow[2] = {-INFINITY, -INFINITY};
    float lrow[2] = {0.f, 0.f};

    int st = 0;
#pragma unroll 1
    for (int c = 0; c < 16; c++) {
        CP_WAIT1();
        __syncthreads();
        {
            const int cn = c + 2;
            if (cn < 16) {
                int stn = st + 2; if (stn >= 3) stn -= 3;
                issue_chunk(cn, stn);
            }
        }
        CP_COMMIT();

        if (c == 0) {
#pragma unroll
            for (int ks = 0; ks < 4; ks++)
                ldsm4(qfh[ks], sb + A_OFF_QH + qoff[ks]);
        }

        const uint32_t kb = sb + A_OFF_KV + st * A_STAGE;
        const uint32_t vbh = kb + 8192;

        float sacc[8][4];
#pragma unroll
        for (int t = 0; t < 8; t++)
#pragma unroll
            for (int q = 0; q < 4; q++) sacc[t][q] = 0.f;
#pragma unroll
        for (int ks = 0; ks < 4; ks++) {
            uint32_t kth[4][4];
#pragma unroll
            for (int np = 0; np < 4; np++)
                ldsm4(kth[np], kb + lbo[np][ks]);
#pragma unroll
            for (int np = 0; np < 4; np++) {
                mma_f16(sacc[2*np],   qfh[ks], kth[np]);
                mma_f16(sacc[2*np+1], qfh[ks], kth[np] + 2);
            }
        }

#pragma unroll
        for (int r = 0; r < 2; r++) {
            float mx = mrow[r];
#pragma unroll
            for (int t = 0; t < 8; t++)
                mx = fmaxf(mx, fmaxf(sacc[t][2*r], sacc[t][2*r+1]));
            mx = fmaxf(mx, __shfl_xor_sync(0xffffffffu, mx, 1));
            mx = fmaxf(mx, __shfl_xor_sync(0xffffffffu, mx, 2));
            const float sc = exp2f(mrow[r] - mx);
            mrow[r] = mx;
            float sum = 0.f;
#pragma unroll
            for (int t = 0; t < 8; t++) {
                float p0 = exp2f(sacc[t][2*r]   - mx);
                float p1 = exp2f(sacc[t][2*r+1] - mx);
                sacc[t][2*r] = p0; sacc[t][2*r+1] = p1;
                sum += p0 + p1;
            }
            sum += __shfl_xor_sync(0xffffffffu, sum, 1);
            sum += __shfl_xor_sync(0xffffffffu, sum, 2);
            lrow[r] = lrow[r] * sc + sum;
#pragma unroll
            for (int t = 0; t < 8; t++) {
                oacc[t][2*r] *= sc; oacc[t][2*r+1] *= sc;
            }
        }

#pragma unroll
        for (int j = 0; j < 4; j++) {
            uint32_t pah[4];
            pah[0] = pack2h(sacc[2*j][0],   sacc[2*j][1]);
            pah[1] = pack2h(sacc[2*j][2],   sacc[2*j][3]);
            pah[2] = pack2h(sacc[2*j+1][0], sacc[2*j+1][1]);
            pah[3] = pack2h(sacc[2*j+1][2], sacc[2*j+1][3]);
            uint32_t vfh[4][4];
#pragma unroll
            for (int dp = 0; dp < 4; dp++)
                ldsm4(vfh[dp], vbh + lbo[dp][j]);
#pragma unroll
            for (int dp = 0; dp < 4; dp++) {
                mma_f16(oacc[2*dp],   pah, vfh[dp]);
                mma_f16(oacc[2*dp+1], pah, vfh[dp] + 2);
            }
        }

        st = (st == 2) ? 0 : st + 1;
    }

    const float inv0 = 1.f / lrow[0];
    const float inv1 = 1.f / lrow[1];
    const int q0 = qt * 128 + wid * 16 + (lane >> 2);
#pragma unroll
    for (int t = 0; t < 8; t++) {
        const int col = h * 64 + t * 8 + (lane & 3) * 2;
        const size_t o0 = ((size_t)(b * L_SZ + q0)) * DM + col;
        const size_t o1 = ((size_t)(b * L_SZ + q0 + 8)) * DM + col;
        *(uint32_t*)(Oh + o0) = pack2h(oacc[t][0] * inv0, oacc[t][1] * inv0);
        *(uint32_t*)(Oh + o1) = pack2h(oacc[t][2] * inv1, oacc[t][3] * inv1);
    }
}

// ============================================================================
// launch
// ============================================================================
extern "C" void kernel_launch(void* const* d_in, const int* in_sizes, int n_in,
                              void* d_out, int out_size)
{
    const float* x     = (const float*)d_in[0];
    const float* w_qkv = (const float*)d_in[1];
    const float* w_o   = (const float*)d_in[2];
    float* out = (float*)d_out;

    __half *xh_p, *wqh_p, *woh_p, *ah_p;
    __half *qh_p, *kh_p, *vth_p;
    cudaGetSymbolAddress((void**)&xh_p,  g_xh);
    cudaGetSymbolAddress((void**)&wqh_p, g_wqh);
    cudaGetSymbolAddress((void**)&woh_p, g_woh);
    cudaGetSymbolAddress((void**)&ah_p,  g_ah);
    cudaGetSymbolAddress((void**)&qh_p,  g_qh);
    cudaGetSymbolAddress((void**)&kh_p,  g_kh);
    cudaGetSymbolAddress((void**)&vth_p, g_vth);

    cudaFuncSetAttribute(gemm_qkv_fused_kernel,
                         cudaFuncAttributeMaxDynamicSharedMemorySize, PGEMM_SMEM);
    cudaFuncSetAttribute(gemm_f16_kernel,
                         cudaFuncAttributeMaxDynamicSharedMemorySize, PGEMM_SMEM);
    cudaFuncSetAttribute(attn_f16_kernel,
                         cudaFuncAttributeMaxDynamicSharedMemorySize, ATTN_SMEM);

    // 0) converts (one launch)
    {
        const int n1 = MROWS * DM / 8, n2 = QKV_E * DM / 8, n3 = DM * DM / 8;
        convert_all_kernel<<<(n1 + n2 + n3 + 255) / 256, 256>>>(
            x, xh_p, n1, w_qkv, wqh_p, n2, w_o, woh_p, n3);
    }
    // 1) QKV projection + fused norm/rope/transpose
    {
        dim3 grid(QKV_E / 128, MROWS / 128);
        gemm_qkv_fused_kernel<<<grid, 256, PGEMM_SMEM>>>(xh_p, wqh_p,
                                                         qh_p, kh_p, vth_p);
    }
    // 2) attention
    {
        dim3 grid(L_SZ / 128, NH, B_SZ);
        attn_f16_kernel<<<grid, 256, ATTN_SMEM>>>(qh_p, kh_p, vth_p, ah_p);
    }
    // 3) output projection
    {
        dim3 grid(DM / 128, MROWS / 128);
        gemm_f16_kernel<<<grid, 256, PGEMM_SMEM>>>(ah_p, woh_p, out, DM, DM);
    }
}

// round 17
// speedup vs baseline: 1.1005x; 1.0372x over previous
#include <cuda_runtime.h>
#include <cuda_fp16.h>
#include <math.h>
#include <stdint.h>

// Problem constants
#define B_SZ 8
#define L_SZ 1024
#define DM 1024
#define NH 16
#define NG 4
#define HD 64
#define QKV_E 1536
#define MROWS (B_SZ * L_SZ)   // 8192

// ---------------- scratch (device globals; no allocation allowed) ----------
__device__ __half g_xh[MROWS * DM];
__device__ __half g_wqh[QKV_E * DM];
__device__ __half g_woh[DM * DM];
__device__ __half g_ah[MROWS * DM];              // attention output
__device__ __half g_qh[B_SZ * NH * L_SZ * HD];
__device__ __half g_kh[B_SZ * NG * L_SZ * HD];
__device__ __half g_vth[B_SZ * NG * HD * L_SZ];  // [b,g,d,l]

// ============================================================================
// helpers
// ============================================================================
__device__ __forceinline__ uint32_t smem_u32(const void* p) {
    uint32_t a;
    asm("{ .reg .u64 t; cvta.to.shared.u64 t, %1; cvt.u32.u64 %0, t; }"
        : "=r"(a) : "l"(p));
    return a;
}

__device__ __forceinline__ void ldsm4(uint32_t* r, uint32_t addr) {
    asm volatile("ldmatrix.sync.aligned.m8n8.x4.shared.b16 {%0,%1,%2,%3}, [%4];"
        : "=r"(r[0]), "=r"(r[1]), "=r"(r[2]), "=r"(r[3]) : "r"(addr));
}

__device__ __forceinline__ void mma_f16(float* d, const uint32_t* a,
                                        const uint32_t* b) {
    asm volatile(
        "mma.sync.aligned.m16n8k16.row.col.f32.f16.f16.f32 "
        "{%0,%1,%2,%3}, {%4,%5,%6,%7}, {%8,%9}, {%0,%1,%2,%3};"
        : "+f"(d[0]), "+f"(d[1]), "+f"(d[2]), "+f"(d[3])
        : "r"(a[0]), "r"(a[1]), "r"(a[2]), "r"(a[3]), "r"(b[0]), "r"(b[1]));
}

__device__ __forceinline__ uint32_t pack2h(float a, float b) {
    __half2 h = __floats2half2_rn(a, b);
    return *(uint32_t*)&h;
}

#define CP16(smem_addr, gptr) \
    asm volatile("cp.async.cg.shared.global [%0], [%1], 16;" :: "r"(smem_addr), "l"(gptr))
#define CP_COMMIT() asm volatile("cp.async.commit_group;" ::: "memory")
#define CP_WAIT1()  asm volatile("cp.async.wait_group 1;" ::: "memory")

// ============================================================================
// Kernel 0: fp32 -> fp16, all three operands in ONE launch
// ============================================================================
__global__ void __launch_bounds__(256) convert_all_kernel(
    const float* __restrict__ x, __half* __restrict__ xh, int n1,
    const float* __restrict__ wq, __half* __restrict__ wqh, int n2,
    const float* __restrict__ wo, __half* __restrict__ woh, int n3)
{
    int i = blockIdx.x * blockDim.x + threadIdx.x;
    const float* src;
    __half* dst;
    if (i < n1)                { src = x;  dst = xh; }
    else if (i < n1 + n2)      { src = wq; dst = wqh; i -= n1; }
    else if (i < n1 + n2 + n3) { src = wo; dst = woh; i -= n1 + n2; }
    else return;
    float4 v0 = ((const float4*)src)[2 * i];
    float4 v1 = ((const float4*)src)[2 * i + 1];
    uint4 hi;
    hi.x = pack2h(v0.x, v0.y);
    hi.y = pack2h(v0.z, v0.w);
    hi.z = pack2h(v1.x, v1.y);
    hi.w = pack2h(v1.z, v1.w);
    ((uint4*)dst)[i] = hi;
}

// ============================================================================
// GEMM: 128x128 CTA, BK=32 chunks processed in PAIRS (64 K per sync).
// 6-stage ring = 3 pair-slots, 2 pairs in flight, ONE sync per 64 HMMAs.
// ============================================================================
#define PSTAGE 16384
#define PGEMM_SMEM (6 * PSTAGE)   // 96KB

// ============================================================================
// Kernel 1a: QKV GEMM + fused norm/RoPE/transpose epilogue.
// Epilogue stages results in warp-private smem, then coalesced uint4 stores.
// ============================================================================
__global__ void __launch_bounds__(256, 2) gemm_qkv_fused_kernel(
    const __half* __restrict__ Ah, const __half* __restrict__ Bh,
    __half* __restrict__ qh, __half* __restrict__ kh, __half* __restrict__ vth)
{
    const int K = DM;
    extern __shared__ char smem[];
    const uint32_t sb = smem_u32(smem);
    const int tid = threadIdx.x;
    const int wid = tid >> 5;
    const int lane = tid & 31;
    const int m0 = blockIdx.y * 128;
    const int n0 = blockIdx.x * 128;
    const int NP = K >> 6;                  // 16 pair-iterations

    const int warp_m = wid & 3;
    const int warp_n = wid >> 2;

    const int lrow = tid >> 1;
    const int swz_l = (lrow >> 1) & 3;
    const uint32_t so0 = lrow * 64 + ((((tid & 1) * 2 + 0) ^ swz_l) << 4);
    const uint32_t so1 = lrow * 64 + ((((tid & 1) * 2 + 1) ^ swz_l) << 4);
    const size_t roA0 = (size_t)(m0 + lrow) * K + (tid & 1) * 16;
    const size_t roB0 = (size_t)(n0 + lrow) * K + (tid & 1) * 16;

    auto issue_pair = [&](int p, int slot) {
        const uint32_t base = sb + slot * 2 * PSTAGE;
#pragma unroll
        for (int half = 0; half < 2; half++) {
            const uint32_t hb = base + half * PSTAGE;
            const size_t ra = roA0 + (2 * p + half) * 32;
            const size_t rb = roB0 + (2 * p + half) * 32;
            CP16(hb + so0,        Ah + ra);
            CP16(hb + so1,        Ah + ra + 8);
            CP16(hb + 8192 + so0, Bh + rb);
            CP16(hb + 8192 + so1, Bh + rb + 8);
        }
    };

    uint32_t aoff[2][2];
#pragma unroll
    for (int tm = 0; tm < 2; tm++) {
        int r = warp_m * 32 + tm * 16 + (lane & 15);
        int sw = (r >> 1) & 3;
#pragma unroll
        for (int ks = 0; ks < 2; ks++) {
            int ch = ks * 2 + (lane >> 4);
            aoff[tm][ks] = r * 64 + ((ch ^ sw) << 4);
        }
    }
    uint32_t boff[4][2];
#pragma unroll
    for (int bp = 0; bp < 4; bp++) {
        int r = warp_n * 64 + bp * 16 + ((lane >> 4) << 3) + (lane & 7);
        int sw = (r >> 1) & 3;
#pragma unroll
        for (int ks = 0; ks < 2; ks++) {
            int ch = ks * 2 + ((lane >> 3) & 1);
            boff[bp][ks] = r * 64 + ((ch ^ sw) << 4);
        }
    }

    float acc[2][8][4];
#pragma unroll
    for (int i = 0; i < 2; i++)
#pragma unroll
        for (int j = 0; j < 8; j++)
#pragma unroll
            for (int q = 0; q < 4; q++) acc[i][j][q] = 0.f;

    issue_pair(0, 0); CP_COMMIT();
    issue_pair(1, 1); CP_COMMIT();

    int slot = 0;
#pragma unroll 1
    for (int p = 0; p < NP; p++) {
        CP_WAIT1();
        __syncthreads();
        {
            const int pn = p + 2;
            if (pn < NP) {
                int sl = slot + 2; if (sl >= 3) sl -= 3;
                issue_pair(pn, sl);
            }
        }
        CP_COMMIT();

        const uint32_t pb = sb + slot * 2 * PSTAGE;
#pragma unroll
        for (int half = 0; half < 2; half++) {
            const uint32_t ah = pb + half * PSTAGE;
            const uint32_t wh = ah + 8192;
#pragma unroll
            for (int ks = 0; ks < 2; ks++) {
                uint32_t fa[2][4];
#pragma unroll
                for (int tm = 0; tm < 2; tm++)
                    ldsm4(fa[tm], ah + aoff[tm][ks]);
                uint32_t fb[8][2];
#pragma unroll
                for (int bp = 0; bp < 4; bp++) {
                    uint32_t t[4];
                    ldsm4(t, wh + boff[bp][ks]);
                    fb[2*bp][0] = t[0]; fb[2*bp][1] = t[1];
                    fb[2*bp+1][0] = t[2]; fb[2*bp+1][1] = t[3];
                }
#pragma unroll
                for (int tm = 0; tm < 2; tm++)
#pragma unroll
                    for (int tn = 0; tn < 8; tn++)
                        mma_f16(acc[tm][tn], fa[tm], fb[tn]);
            }
        }
        slot = (slot == 2) ? 0 : slot + 1;
    }

    // ---- FUSED epilogue: norm + rope, staged via smem, coalesced stores ----
    __syncthreads();   // pipeline smem is now free for staging
    const int er = lane >> 2;
    const int jb = lane & 3;              // j = tn*4 + jb
    const int slot_h = blockIdx.x * 2 + warp_n;

    const int mbase = m0 + warp_m * 32;
    const int b = mbase >> 10;
    const int l0 = mbase & 1023;          // 32 consecutive l for this warp

    __half* stg = (__half*)(smem + wid * 8192);

    float invf[8];
#pragma unroll
    for (int tn = 0; tn < 8; tn++)
        invf[tn] = exp2f(-0.41524101186098287f * (float)(tn * 4 + jb));

    if (slot_h < 20) {
        // ---- q/k: stage [row32][j64] at stride 72 halves ----
#pragma unroll
        for (int tm = 0; tm < 2; tm++) {
#pragma unroll
            for (int rr = 0; rr < 2; rr++) {
                const int lr = tm * 16 + rr * 8 + er;
                const int q0 = 2 * rr, q1 = 2 * rr + 1;
                float ss = 0.f;
#pragma unroll
                for (int tn = 0; tn < 8; tn++)
                    ss += acc[tm][tn][q0] * acc[tm][tn][q0]
                        + acc[tm][tn][q1] * acc[tm][tn][q1];
                ss += __shfl_xor_sync(0xffffffffu, ss, 1);
                ss += __shfl_xor_sync(0xffffffffu, ss, 2);
                float inv = 1.f / (sqrtf(ss) + 1e-10f);
                if (slot_h < 16) inv *= 0.18033688011112042f;  // 0.125*log2(e)

                const int l = l0 + lr;
                const float psum = (float)((l >> 5) + (l & 31));
#pragma unroll
                for (int tn = 0; tn < 8; tn++) {
                    const int j = tn * 4 + jb;
                    const float fr = psum * invf[tn];
                    float s, c;
                    __sincosf(fr, &s, &c);
                    const float x1 = acc[tm][tn][q0] * inv;
                    const float x2 = acc[tm][tn][q1] * inv;
                    stg[lr * 72 + j]      = __float2half_rn(x1 * c - x2 * s);
                    stg[lr * 72 + j + 32] = __float2half_rn(x1 * s + x2 * c);
                }
            }
        }
        __syncwarp();
        // bulk store: 32 rows x 128B contiguous in global
        __half* dst;
        if (slot_h < 16)
            dst = qh + (((size_t)b * NH + slot_h) * L_SZ + l0) * HD;
        else
            dst = kh + (((size_t)b * NG + (slot_h - 16)) * L_SZ + l0) * HD;
        uint4* g4 = (uint4*)dst;
#pragma unroll
        for (int i = 0; i < 8; i++) {
            const int idx = i * 32 + lane;
            const int row = idx >> 3, k = idx & 7;
            g4[idx] = *(const uint4*)(stg + row * 72 + k * 8);
        }
    } else {
        // ---- v: stage [d64][lr32] at stride 40 halves (16B aligned) ----
#pragma unroll
        for (int tm = 0; tm < 2; tm++) {
#pragma unroll
            for (int rr = 0; rr < 2; rr++) {
                const int lr = tm * 16 + rr * 8 + er;
                const int q0 = 2 * rr, q1 = 2 * rr + 1;
#pragma unroll
                for (int tn = 0; tn < 8; tn++) {
                    const int d0 = tn * 8 + jb * 2;
                    stg[d0 * 40 + lr]       = __float2half_rn(acc[tm][tn][q0]);
                    stg[(d0 + 1) * 40 + lr] = __float2half_rn(acc[tm][tn][q1]);
                }
            }
        }
        __syncwarp();
        // bulk store: 64 d-rows x 64B contiguous runs
        __half* vdst = vth + ((size_t)(b * NG + slot_h - 20) * HD) * L_SZ + l0;
#pragma unroll
        for (int i = 0; i < 8; i++) {
            const int idx = i * 32 + lane;
            const int d = idx >> 2, part = idx & 3;
            *(uint4*)(vdst + (size_t)d * L_SZ + part * 8) =
                *(const uint4*)(stg + d * 40 + part * 8);
        }
    }
}

// ============================================================================
// Kernel 1b: plain GEMM (out-projection): C fp32 = A[M,K] @ B[N,K]^T
// ============================================================================
__global__ void __launch_bounds__(256, 2) gemm_f16_kernel(
    const __half* __restrict__ Ah, const __half* __restrict__ Bh,
    float* __restrict__ C, int N, int K)
{
    extern __shared__ char smem[];
    const uint32_t sb = smem_u32(smem);
    const int tid = threadIdx.x;
    const int wid = tid >> 5;
    const int lane = tid & 31;
    const int m0 = blockIdx.y * 128;
    const int n0 = blockIdx.x * 128;
    const int NP = K >> 6;

    const int warp_m = wid & 3;
    const int warp_n = wid >> 2;

    const int lrow = tid >> 1;
    const int swz_l = (lrow >> 1) & 3;
    const uint32_t so0 = lrow * 64 + ((((tid & 1) * 2 + 0) ^ swz_l) << 4);
    const uint32_t so1 = lrow * 64 + ((((tid & 1) * 2 + 1) ^ swz_l) << 4);
    const size_t roA0 = (size_t)(m0 + lrow) * K + (tid & 1) * 16;
    const size_t roB0 = (size_t)(n0 + lrow) * K + (tid & 1) * 16;

    auto issue_pair = [&](int p, int slot) {
        const uint32_t base = sb + slot * 2 * PSTAGE;
#pragma unroll
        for (int half = 0; half < 2; half++) {
            const uint32_t hb = base + half * PSTAGE;
            const size_t ra = roA0 + (2 * p + half) * 32;
            const size_t rb = roB0 + (2 * p + half) * 32;
            CP16(hb + so0,        Ah + ra);
            CP16(hb + so1,        Ah + ra + 8);
            CP16(hb + 8192 + so0, Bh + rb);
            CP16(hb + 8192 + so1, Bh + rb + 8);
        }
    };

    uint32_t aoff[2][2];
#pragma unroll
    for (int tm = 0; tm < 2; tm++) {
        int r = warp_m * 32 + tm * 16 + (lane & 15);
        int sw = (r >> 1) & 3;
#pragma unroll
        for (int ks = 0; ks < 2; ks++) {
            int ch = ks * 2 + (lane >> 4);
            aoff[tm][ks] = r * 64 + ((ch ^ sw) << 4);
        }
    }
    uint32_t boff[4][2];
#pragma unroll
    for (int bp = 0; bp < 4; bp++) {
        int r = warp_n * 64 + bp * 16 + ((lane >> 4) << 3) + (lane & 7);
        int sw = (r >> 1) & 3;
#pragma unroll
        for (int ks = 0; ks < 2; ks++) {
            int ch = ks * 2 + ((lane >> 3) & 1);
            boff[bp][ks] = r * 64 + ((ch ^ sw) << 4);
        }
    }

    float acc[2][8][4];
#pragma unroll
    for (int i = 0; i < 2; i++)
#pragma unroll
        for (int j = 0; j < 8; j++)
#pragma unroll
            for (int q = 0; q < 4; q++) acc[i][j][q] = 0.f;

    issue_pair(0, 0); CP_COMMIT();
    issue_pair(1, 1); CP_COMMIT();

    int slot = 0;
#pragma unroll 1
    for (int p = 0; p < NP; p++) {
        CP_WAIT1();
        __syncthreads();
        {
            const int pn = p + 2;
            if (pn < NP) {
                int sl = slot + 2; if (sl >= 3) sl -= 3;
                issue_pair(pn, sl);
            }
        }
        CP_COMMIT();

        const uint32_t pb = sb + slot * 2 * PSTAGE;
#pragma unroll
        for (int half = 0; half < 2; half++) {
            const uint32_t ah = pb + half * PSTAGE;
            const uint32_t wh = ah + 8192;
#pragma unroll
            for (int ks = 0; ks < 2; ks++) {
                uint32_t fa[2][4];
#pragma unroll
                for (int tm = 0; tm < 2; tm++)
                    ldsm4(fa[tm], ah + aoff[tm][ks]);
                uint32_t fb[8][2];
#pragma unroll
                for (int bp = 0; bp < 4; bp++) {
                    uint32_t t[4];
                    ldsm4(t, wh + boff[bp][ks]);
                    fb[2*bp][0] = t[0]; fb[2*bp][1] = t[1];
                    fb[2*bp+1][0] = t[2]; fb[2*bp+1][1] = t[3];
                }
#pragma unroll
                for (int tm = 0; tm < 2; tm++)
#pragma unroll
                    for (int tn = 0; tn < 8; tn++)
                        mma_f16(acc[tm][tn], fa[tm], fb[tn]);
            }
        }
        slot = (slot == 2) ? 0 : slot + 1;
    }

    const int er = lane >> 2;
    const int ec = (lane & 3) * 2;
#pragma unroll
    for (int tm = 0; tm < 2; tm++) {
        const int rbase = m0 + warp_m * 32 + tm * 16 + er;
#pragma unroll
        for (int tn = 0; tn < 8; tn++) {
            const int cbase = n0 + warp_n * 64 + tn * 8 + ec;
            float* p0 = C + (size_t)rbase * N + cbase;
            float* p1 = C + (size_t)(rbase + 8) * N + cbase;
            *(float2*)p0 = make_float2(acc[tm][tn][0], acc[tm][tn][1]);
            *(float2*)p1 = make_float2(acc[tm][tn][2], acc[tm][tn][3]);
        }
    }
}

// ============================================================================
// Kernel 2: tensor-core flash attention (unchanged).
// ============================================================================
#define A_OFF_QH 0
#define A_OFF_KV 16384
#define A_STAGE  16384
#define ATTN_SMEM (A_OFF_KV + 3 * A_STAGE)   // 65536

__global__ void __launch_bounds__(256, 2) attn_f16_kernel(
    const __half* __restrict__ qh, const __half* __restrict__ kh,
    const __half* __restrict__ vth,
    __half* __restrict__ Oh)
{
    extern __shared__ char smem[];
    const uint32_t sb = smem_u32(smem);
    const int tid = threadIdx.x;
    const int wid = tid >> 5;
    const int lane = tid & 31;

    const int qt = blockIdx.x;
    const int h = blockIdx.y;
    const int b = blockIdx.z;
    const int g = h >> 2;

    const __half* Qh_g = qh + ((((size_t)b * NH + h) * L_SZ) + qt * 128) * HD;
    const __half* Kh_g = kh + (((size_t)b * NG + g) * L_SZ) * HD;
    const __half* Vth_g = vth + ((size_t)b * NG + g) * HD * L_SZ;

#pragma unroll
    for (int i = 0; i < 4; i++) {
        int idx = tid * 4 + i;
        int row = idx >> 3, ch = idx & 7;
        uint32_t sw = (uint32_t)(row * 128 + ((ch ^ (row & 7)) << 4));
        CP16(sb + A_OFF_QH + sw, Qh_g + row * 64 + ch * 8);
    }

    auto issue_chunk = [&](int c, int st) {
        const uint32_t base = sb + A_OFF_KV + st * A_STAGE;
#pragma unroll
        for (int i = 0; i < 2; i++) {
            int idx = tid * 2 + i;
            int row = idx >> 3, ch = idx & 7;
            uint32_t sw = (uint32_t)(row * 128 + ((ch ^ (row & 7)) << 4));
            CP16(base + sw,        Kh_g + (size_t)(c * 64 + row) * 64 + ch * 8);
            CP16(base + 8192 + sw, Vth_g + (size_t)row * L_SZ + c * 64 + ch * 8);
        }
    };

    issue_chunk(0, 0);
    CP_COMMIT();
    issue_chunk(1, 1);
    CP_COMMIT();

    uint32_t qoff[4];
#pragma unroll
    for (int ks = 0; ks < 4; ks++) {
        int r = wid * 16 + (lane & 15);
        int ch = ks * 2 + (lane >> 4);
        qoff[ks] = (uint32_t)(r * 128 + ((ch ^ (r & 7)) << 4));
    }
    uint32_t lbo[4][4];
#pragma unroll
    for (int np = 0; np < 4; np++) {
        int r = np * 16 + ((lane >> 4) << 3) + (lane & 7);
#pragma unroll
        for (int ks = 0; ks < 4; ks++) {
            int ch = ks * 2 + ((lane >> 3) & 1);
            lbo[np][ks] = (uint32_t)(r * 128 + ((ch ^ (r & 7)) << 4));
        }
    }

    uint32_t qfh[4][4];
    float oacc[8][4];
#pragma unroll
    for (int t = 0; t < 8; t++)
#pragma unroll
        for (int q = 0; q < 4; q++) oacc[t][q] = 0.f;
    float mrow[2] = {-INFINITY, -INFINITY};
    float lrow[2] = {0.f, 0.f};

    int st = 0;
#pragma unroll 1
    for (int c = 0; c < 16; c++) {
        CP_WAIT1();
        __syncthreads();
        {
            const int cn = c + 2;
            if (cn < 16) {
                int stn = st + 2; if (stn >= 3) stn -= 3;
                issue_chunk(cn, stn);
            }
        }
        CP_COMMIT();

        if (c == 0) {
#pragma unroll
            for (int ks = 0; ks < 4; ks++)
                ldsm4(qfh[ks], sb + A_OFF_QH + qoff[ks]);
        }

        const uint32_t kb = sb + A_OFF_KV + st * A_STAGE;
        const uint32_t vbh = kb + 8192;

        float sacc[8][4];
#pragma unroll
        for (int t = 0; t < 8; t++)
#pragma unroll
            for (int q = 0; q < 4; q++) sacc[t][q] = 0.f;
#pragma unroll
        for (int ks = 0; ks < 4; ks++) {
            uint32_t kth[4][4];
#pragma unroll
            for (int np = 0; np < 4; np++)
                ldsm4(kth[np], kb + lbo[np][ks]);
#pragma unroll
            for (int np = 0; np < 4; np++) {
                mma_f16(sacc[2*np],   qfh[ks], kth[np]);
                mma_f16(sacc[2*np+1], qfh[ks], kth[np] + 2);
            }
        }

#pragma unroll
        for (int r = 0; r < 2; r++) {
            float mx = mrow[r];
#pragma unroll
            for (int t = 0; t < 8; t++)
                mx = fmaxf(mx, fmaxf(sacc[t][2*r], sacc[t][2*r+1]));
            mx = fmaxf(mx, __shfl_xor_sync(0xffffffffu, mx, 1));
            mx = fmaxf(mx, __shfl_xor_sync(0xffffffffu, mx, 2));
            const float sc = exp2f(mrow[r] - mx);
            mrow[r] = mx;
            float sum = 0.f;
#pragma unroll
            for (int t = 0; t < 8; t++) {
                float p0 = exp2f(sacc[t][2*r]   - mx);
                float p1 = exp2f(sacc[t][2*r+1] - mx);
                sacc[t][2*r] = p0; sacc[t][2*r+1] = p1;
                sum += p0 + p1;
            }
            sum += __shfl_xor_sync(0xffffffffu, sum, 1);
            sum += __shfl_xor_sync(0xffffffffu, sum, 2);
            lrow[r] = lrow[r] * sc + sum;
#pragma unroll
            for (int t = 0; t < 8; t++) {
                oacc[t][2*r] *= sc; oacc[t][2*r+1] *= sc;
            }
        }

#pragma unroll
        for (int j = 0; j < 4; j++) {
            uint32_t pah[4];
            pah[0] = pack2h(sacc[2*j][0],   sacc[2*j][1]);
            pah[1] = pack2h(sacc[2*j][2],   sacc[2*j][3]);
            pah[2] = pack2h(sacc[2*j+1][0], sacc[2*j+1][1]);
            pah[3] = pack2h(sacc[2*j+1][2], sacc[2*j+1][3]);
            uint32_t vfh[4][4];
#pragma unroll
            for (int dp = 0; dp < 4; dp++)
                ldsm4(vfh[dp], vbh + lbo[dp][j]);
#pragma unroll
            for (int dp = 0; dp < 4; dp++) {
                mma_f16(oacc[2*dp],   pah, vfh[dp]);
                mma_f16(oacc[2*dp+1], pah, vfh[dp] + 2);
            }
        }

        st = (st == 2) ? 0 : st + 1;
    }

    const float inv0 = 1.f / lrow[0];
    const float inv1 = 1.f / lrow[1];
    const int q0 = qt * 128 + wid * 16 + (lane >> 2);
#pragma unroll
    for (int t = 0; t < 8; t++) {
        const int col = h * 64 + t * 8 + (lane & 3) * 2;
        const size_t o0 = ((size_t)(b * L_SZ + q0)) * DM + col;
        const size_t o1 = ((size_t)(b * L_SZ + q0 + 8)) * DM + col;
        *(uint32_t*)(Oh + o0) = pack2h(oacc[t][0] * inv0, oacc[t][1] * inv0);
        *(uint32_t*)(Oh + o1) = pack2h(oacc[t][2] * inv1, oacc[t][3] * inv1);
    }
}

// ============================================================================
// launch
// ============================================================================
extern "C" void kernel_launch(void* const* d_in, const int* in_sizes, int n_in,
                              void* d_out, int out_size)
{
    const float* x     = (const float*)d_in[0];
    const float* w_qkv = (const float*)d_in[1];
    const float* w_o   = (const float*)d_in[2];
    float* out = (float*)d_out;

    __half *xh_p, *wqh_p, *woh_p, *ah_p;
    __half *qh_p, *kh_p, *vth_p;
    cudaGetSymbolAddress((void**)&xh_p,  g_xh);
    cudaGetSymbolAddress((void**)&wqh_p, g_wqh);
    cudaGetSymbolAddress((void**)&woh_p, g_woh);
    cudaGetSymbolAddress((void**)&ah_p,  g_ah);
    cudaGetSymbolAddress((void**)&qh_p,  g_qh);
    cudaGetSymbolAddress((void**)&kh_p,  g_kh);
    cudaGetSymbolAddress((void**)&vth_p, g_vth);

    cudaFuncSetAttribute(gemm_qkv_fused_kernel,
                         cudaFuncAttributeMaxDynamicSharedMemorySize, PGEMM_SMEM);
    cudaFuncSetAttribute(gemm_f16_kernel,
                         cudaFuncAttributeMaxDynamicSharedMemorySize, PGEMM_SMEM);
    cudaFuncSetAttribute(attn_f16_kernel,
                         cudaFuncAttributeMaxDynamicSharedMemorySize, ATTN_SMEM);

    // 0) converts (one launch)
    {
        const int n1 = MROWS * DM / 8, n2 = QKV_E * DM / 8, n3 = DM * DM / 8;
        convert_all_kernel<<<(n1 + n2 + n3 + 255) / 256, 256>>>(
            x, xh_p, n1, w_qkv, wqh_p, n2, w_o, woh_p, n3);
    }
    // 1) QKV projection + fused norm/rope/transpose
    {
        dim3 grid(QKV_E / 128, MROWS / 128);
        gemm_qkv_fused_kernel<<<grid, 256, PGEMM_SMEM>>>(xh_p, wqh_p,
                                                         qh_p, kh_p, vth_p);
    }
    // 2) attention
    {
        dim3 grid(L_SZ / 128, NH, B_SZ);
        attn_f16_kernel<<<grid, 256, ATTN_SMEM>>>(qh_p, kh_p, vth_p, ah_p);
    }
    // 3) output projection
    {
        dim3 grid(DM / 128, MROWS / 128);
        gemm_f16_kernel<<<grid, 256, PGEMM_SMEM>>>(ah_p, woh_p, out, DM, DM);
    }
}